// round 9
// baseline (speedup 1.0000x reference)
#include <cuda_runtime.h>
#include <cuda_fp16.h>
#include <math.h>
#include <stdint.h>

#define S_DIM 128
#define L_DIM 384
#define DM 256
#define NH 8
#define HD 32
#define RTOT (S_DIM * L_DIM)           // 49152
#define ATT_SCALE_LOG2E 0.25501689767769175f  // (1/sqrt(32)) * log2(e)

// ---------------- scratch ----------------------------------------------------
__device__ __half g_wq16[DM * DM];
__device__ __half g_wk16[DM * DM];
__device__ __half g_wv16[DM * DM];
__device__ __half g_wo16[DM * DM];
__device__ __half g_q16[RTOT * DM];
__device__ __half g_k16[RTOT * DM];
__device__ __half g_v16[RTOT * DM];
__device__ __half g_ao16[RTOT * DM];

// ---------------- PTX helpers ------------------------------------------------
__device__ __forceinline__ void mma16816(float* d, const uint32_t* a, const uint32_t* b)
{
    asm volatile(
        "mma.sync.aligned.m16n8k16.row.col.f32.f16.f16.f32 "
        "{%0,%1,%2,%3}, {%4,%5,%6,%7}, {%8,%9}, {%0,%1,%2,%3};\n"
        : "+f"(d[0]), "+f"(d[1]), "+f"(d[2]), "+f"(d[3])
        : "r"(a[0]), "r"(a[1]), "r"(a[2]), "r"(a[3]), "r"(b[0]), "r"(b[1]));
}
__device__ __forceinline__ uint32_t s2u(const void* p)
{
    return (uint32_t)__cvta_generic_to_shared(p);
}
__device__ __forceinline__ void ldsm4(uint32_t* r, uint32_t a)
{
    asm volatile("ldmatrix.sync.aligned.m8n8.x4.shared.b16 {%0,%1,%2,%3}, [%4];\n"
                 : "=r"(r[0]), "=r"(r[1]), "=r"(r[2]), "=r"(r[3]) : "r"(a));
}
__device__ __forceinline__ void ldsm4t(uint32_t* r, uint32_t a)
{
    asm volatile("ldmatrix.sync.aligned.m8n8.x4.trans.shared.b16 {%0,%1,%2,%3}, [%4];\n"
                 : "=r"(r[0]), "=r"(r[1]), "=r"(r[2]), "=r"(r[3]) : "r"(a));
}
__device__ __forceinline__ void cpa16(uint32_t dst, const void* src)
{
    asm volatile("cp.async.cg.shared.global [%0], [%1], 16;\n" :: "r"(dst), "l"(src));
}
#define CP_COMMIT asm volatile("cp.async.commit_group;\n" ::: "memory")
#define CP_WAIT0  asm volatile("cp.async.wait_group 0;\n" ::: "memory")
#define CP_WAIT1  asm volatile("cp.async.wait_group 1;\n" ::: "memory")

__device__ __forceinline__ uint32_t pack2(float a, float b)
{
    __half2 h = __floats2half2_rn(a, b);
    return *(uint32_t*)&h;
}

// ---------------- weight conversion (fp32 -> fp16) ---------------------------
__global__ __launch_bounds__(256) void convertW(
    const float* __restrict__ wq, const float* __restrict__ wk,
    const float* __restrict__ wv, const float* __restrict__ wo)
{
    const int t = blockIdx.x * blockDim.x + threadIdx.x;   // 0..32767
    float2 v;
    v = ((const float2*)wq)[t]; ((__half2*)g_wq16)[t] = __floats2half2_rn(v.x, v.y);
    v = ((const float2*)wk)[t]; ((__half2*)g_wk16)[t] = __floats2half2_rn(v.x, v.y);
    v = ((const float2*)wv)[t]; ((__half2*)g_wv16)[t] = __floats2half2_rn(v.x, v.y);
    v = ((const float2*)wo)[t]; ((__half2*)g_wo16)[t] = __floats2half2_rn(v.x, v.y);
}

// ---------------- fat-tile chunk compute (warp 64x64, 32 k-depth) ------------
// As: [128][40], Ws: [256][40]. 16 ldsm.x4 feed 64 mma per warp per chunk.
__device__ __forceinline__ void gemm_chunk2(
    const __half* __restrict__ As, const __half* __restrict__ Ws,
    float acc[4][8][4], int wm, int wn, int lane)
{
    const int ar = lane & 15;
    const int ac = (lane >> 4) * 8;
    const int br = (lane & 7) + ((lane & 16) >> 1);
    const int bc = lane & 8;
    #pragma unroll
    for (int ks = 0; ks < 2; ks++) {
        uint32_t af[4][4], bf[4][4];
        #pragma unroll
        for (int mi = 0; mi < 4; mi++)
            ldsm4(af[mi], s2u(As + (wm + mi * 16 + ar) * 40 + ks * 16 + ac));
        #pragma unroll
        for (int ni = 0; ni < 4; ni++)
            ldsm4(bf[ni], s2u(Ws + (wn + ni * 16 + br) * 40 + ks * 16 + bc));
        #pragma unroll
        for (int mi = 0; mi < 4; mi++)
            #pragma unroll
            for (int ni = 0; ni < 4; ni++) {
                mma16816(acc[mi][2 * ni],     af[mi], bf[ni]);
                mma16816(acc[mi][2 * ni + 1], af[mi], bf[ni] + 2);
            }
    }
}

// smem layout (halfs): As stage s at s*5120 (128x40); Ws stage s at 15360+s*10240 (256x40)
#define GEMM_SMEM 92160

// ---------------- fused QKV GEMM: A = fp32 msa (LDG->cvt->STS) ---------------
// grid (3, 384): blockIdx.x = weight, rt = blockIdx.y*128. N = 256 (full).
__global__ __launch_bounds__(256) void qkv_gemm(const float* __restrict__ X)
{
    extern __shared__ __half dsm[];
    const int wIdx = blockIdx.x;
    const int rt = blockIdx.y * 128;
    const __half* __restrict__ W =
        (wIdx == 0) ? g_wq16 : (wIdx == 1) ? g_wk16 : g_wv16;
    __half* __restrict__ outH =
        (wIdx == 0) ? g_q16 : (wIdx == 1) ? g_k16 : g_v16;

    const int tid = threadIdx.x;
    const int lane = tid & 31;
    const int wid = tid >> 5;
    const int wm = (wid >> 2) * 64;
    const int wn = (wid & 3) * 64;

    const int arow = tid >> 1;            // 0..127
    const int acol = (tid & 1) * 16;      // float col offset

    float pa[16];
    auto ldgA = [&](int kc) {
        const float4* p = (const float4*)&X[(size_t)(rt + arow) * DM + kc + acol];
        *(float4*)&pa[0]  = p[0]; *(float4*)&pa[4]  = p[1];
        *(float4*)&pa[8]  = p[2]; *(float4*)&pa[12] = p[3];
    };
    auto stsA = [&](int buf) {
        uint32_t h[8];
        #pragma unroll
        for (int i = 0; i < 8; i++) h[i] = pack2(pa[2 * i], pa[2 * i + 1]);
        __half* as_ = dsm + buf * 5120;
        *(uint4*)(as_ + arow * 40 + acol)     = *(uint4*)&h[0];
        *(uint4*)(as_ + arow * 40 + acol + 8) = *(uint4*)&h[4];
    };
    auto cpB = [&](int kc, int buf) {
        __half* ws_ = dsm + 15360 + buf * 10240;
        #pragma unroll
        for (int i = 0; i < 4; i++)
            cpa16(s2u(ws_ + tid * 40 + i * 8), &W[(size_t)tid * DM + kc + i * 8]);
        CP_COMMIT;
    };

    float acc[4][8][4] = {};

    ldgA(0); stsA(0);
    cpB(0, 0);
    ldgA(32);              // chunk 1 into regs
    cpB(32, 1);

    #pragma unroll
    for (int kc = 0; kc < 8; kc++) {
        if (kc == 7) { CP_WAIT0; } else { CP_WAIT1; }
        __syncthreads();
        if (kc + 1 < 8) stsA((kc + 1) % 3);
        if (kc + 2 < 8) { ldgA((kc + 2) * 32); cpB((kc + 2) * 32, (kc + 2) % 3); }
        gemm_chunk2(dsm + (kc % 3) * 5120, dsm + 15360 + (kc % 3) * 10240,
                    acc, wm, wn, lane);
    }

    const int g = lane >> 2;
    const int q = lane & 3;
    #pragma unroll
    for (int mi = 0; mi < 4; mi++)
        #pragma unroll
        for (int ni = 0; ni < 8; ni++) {
            int row = rt + wm + mi * 16 + g;
            int col = wn + ni * 8 + q * 2;
            *(__half2*)&outH[(size_t)row * DM + col] =
                __floats2half2_rn(acc[mi][ni][0], acc[mi][ni][1]);
            *(__half2*)&outH[(size_t)(row + 8) * DM + col] =
                __floats2half2_rn(acc[mi][ni][2], acc[mi][ni][3]);
        }
}

// ---------------- output GEMM: A fp16 (g_ao16), out fp32, N = 256 ------------
__global__ __launch_bounds__(256) void out_gemm(float* __restrict__ outF)
{
    extern __shared__ __half dsm[];
    const int rt = blockIdx.x * 128;
    const int tid = threadIdx.x;
    const int lane = tid & 31;
    const int wid = tid >> 5;
    const int wm = (wid >> 2) * 64;
    const int wn = (wid & 3) * 64;

    const int ar2 = tid >> 1;
    const int as2 = (tid & 1) * 2;

    auto cpAB = [&](int kc, int buf) {
        __half* as_ = dsm + buf * 5120;
        __half* ws_ = dsm + 15360 + buf * 10240;
        cpa16(s2u(as_ + ar2 * 40 + as2 * 8),
              &g_ao16[(size_t)(rt + ar2) * DM + kc + as2 * 8]);
        cpa16(s2u(as_ + ar2 * 40 + (as2 + 1) * 8),
              &g_ao16[(size_t)(rt + ar2) * DM + kc + (as2 + 1) * 8]);
        #pragma unroll
        for (int i = 0; i < 4; i++)
            cpa16(s2u(ws_ + tid * 40 + i * 8), &g_wo16[(size_t)tid * DM + kc + i * 8]);
        CP_COMMIT;
    };

    float acc[4][8][4] = {};

    cpAB(0, 0);
    cpAB(32, 1);

    #pragma unroll
    for (int kc = 0; kc < 8; kc++) {
        if (kc == 7) { CP_WAIT0; } else { CP_WAIT1; }
        __syncthreads();
        if (kc + 2 < 8) cpAB((kc + 2) * 32, (kc + 2) % 3);
        gemm_chunk2(dsm + (kc % 3) * 5120, dsm + 15360 + (kc % 3) * 10240,
                    acc, wm, wn, lane);
    }

    const int g = lane >> 2;
    const int q = lane & 3;
    #pragma unroll
    for (int mi = 0; mi < 4; mi++)
        #pragma unroll
        for (int ni = 0; ni < 8; ni++) {
            int row = rt + wm + mi * 16 + g;
            int col = wn + ni * 8 + q * 2;
            *(float2*)&outF[(size_t)row * DM + col] =
                make_float2(acc[mi][ni][0], acc[mi][ni][1]);
            *(float2*)&outF[(size_t)(row + 8) * DM + col] =
                make_float2(acc[mi][ni][2], acc[mi][ni][3]);
        }
}

// ---------------- attention (unchanged from round 7) --------------------------
__global__ __launch_bounds__(384) void attn16()
{
    extern __shared__ __half sh[];
    __half (*Qs)[40] = (__half(*)[40])sh;
    __half (*Ks)[40] = (__half(*)[40])(sh + 384 * 40);
    __half (*Vs)[40] = (__half(*)[40])(sh + 2 * 384 * 40);

    const int s = blockIdx.x >> 3;
    const int h = blockIdx.x & 7;
    const size_t base = (size_t)s * L_DIM;
    const int tid = threadIdx.x;
    const int lane = tid & 31;
    const int wid = tid >> 5;
    const int g = lane >> 2;
    const int q = lane & 3;
    const int wq = wid * 32;

    {
        const __half* qp = &g_q16[(base + tid) * DM + h * HD];
        const __half* kp = &g_k16[(base + tid) * DM + h * HD];
        const __half* vp = &g_v16[(base + tid) * DM + h * HD];
        #pragma unroll
        for (int u = 0; u < 4; u++) {
            cpa16(s2u(&Qs[tid][u * 8]), qp + u * 8);
            cpa16(s2u(&Ks[tid][u * 8]), kp + u * 8);
            cpa16(s2u(&Vs[tid][u * 8]), vp + u * 8);
        }
        CP_COMMIT;
    }
    CP_WAIT0;
    __syncthreads();

    const int ar = (lane & 15);
    const int ac = (lane >> 4) * 8;
    const int br = (lane & 7) + ((lane & 16) >> 1);
    const int bc = (lane & 8);
    const int tr = (lane & 15);
    const int tc = (lane >> 4) * 8;

    uint32_t qf[2][2][4];
    #pragma unroll
    for (int mi = 0; mi < 2; mi++)
        #pragma unroll
        for (int ks = 0; ks < 2; ks++)
            ldsm4(qf[mi][ks], s2u(&Qs[wq + mi * 16 + ar][ks * 16 + ac]));

    float oacc[2][4][4] = {};
    float lsum[2][2] = {};

    #pragma unroll
    for (int kt = 0; kt < L_DIM; kt += 64) {
        #pragma unroll
        for (int nip = 0; nip < 4; nip++) {
            const int kr = kt + nip * 16;
            uint32_t kf0[4], kf1[4], vf0[4], vf1[4];
            ldsm4(kf0, s2u(&Ks[kr + br][bc]));
            ldsm4(kf1, s2u(&Ks[kr + br][16 + bc]));
            ldsm4t(vf0, s2u(&Vs[kr + tr][tc]));
            ldsm4t(vf1, s2u(&Vs[kr + tr][16 + tc]));

            float sacc[2][2][4] = {};
            #pragma unroll
            for (int mi = 0; mi < 2; mi++) {
                #pragma unroll
                for (int ni = 0; ni < 2; ni++) {
                    mma16816(sacc[mi][ni], qf[mi][0], kf0 + 2 * ni);
                    mma16816(sacc[mi][ni], qf[mi][1], kf1 + 2 * ni);
                }
            }

            uint32_t pf[2][4];
            #pragma unroll
            for (int mi = 0; mi < 2; mi++)
                #pragma unroll
                for (int ni = 0; ni < 2; ni++) {
                    float p0 = exp2f(sacc[mi][ni][0] * ATT_SCALE_LOG2E);
                    float p1 = exp2f(sacc[mi][ni][1] * ATT_SCALE_LOG2E);
                    float p2 = exp2f(sacc[mi][ni][2] * ATT_SCALE_LOG2E);
                    float p3 = exp2f(sacc[mi][ni][3] * ATT_SCALE_LOG2E);
                    lsum[mi][0] += p0 + p1;
                    lsum[mi][1] += p2 + p3;
                    pf[mi][ni * 2 + 0] = pack2(p0, p1);
                    pf[mi][ni * 2 + 1] = pack2(p2, p3);
                }

            #pragma unroll
            for (int mi = 0; mi < 2; mi++) {
                mma16816(oacc[mi][0], pf[mi], vf0);
                mma16816(oacc[mi][1], pf[mi], vf0 + 2);
                mma16816(oacc[mi][2], pf[mi], vf1);
                mma16816(oacc[mi][3], pf[mi], vf1 + 2);
            }
        }
    }

    float inv[2][2];
    #pragma unroll
    for (int mi = 0; mi < 2; mi++)
        #pragma unroll
        for (int hi = 0; hi < 2; hi++) {
            float l = lsum[mi][hi];
            l += __shfl_xor_sync(0xffffffffu, l, 1);
            l += __shfl_xor_sync(0xffffffffu, l, 2);
            inv[mi][hi] = 1.0f / l;
        }

    #pragma unroll
    for (int mi = 0; mi < 2; mi++)
        #pragma unroll
        for (int ni = 0; ni < 4; ni++) {
            size_t row = base + wq + mi * 16 + g;
            int col = h * HD + ni * 8 + q * 2;
            *(__half2*)&g_ao16[row * DM + col] =
                __floats2half2_rn(oacc[mi][ni][0] * inv[mi][0],
                                  oacc[mi][ni][1] * inv[mi][0]);
            *(__half2*)&g_ao16[(row + 8) * DM + col] =
                __floats2half2_rn(oacc[mi][ni][2] * inv[mi][1],
                                  oacc[mi][ni][3] * inv[mi][1]);
        }
}

// ---------------- launch -----------------------------------------------------
extern "C" void kernel_launch(void* const* d_in, const int* in_sizes, int n_in,
                              void* d_out, int out_size)
{
    (void)in_sizes; (void)n_in; (void)out_size;
    const float* msa = (const float*)d_in[0];
    const float* Wq  = (const float*)d_in[2];
    const float* Wk  = (const float*)d_in[3];
    const float* Wv  = (const float*)d_in[4];
    const float* Wo  = (const float*)d_in[5];
    float* out = (float*)d_out;

    const int attn_smem = 3 * 384 * 40 * (int)sizeof(__half);     // 92160
    cudaFuncSetAttribute(qkv_gemm, cudaFuncAttributeMaxDynamicSharedMemorySize, GEMM_SMEM);
    cudaFuncSetAttribute(out_gemm, cudaFuncAttributeMaxDynamicSharedMemorySize, GEMM_SMEM);
    cudaFuncSetAttribute(attn16,   cudaFuncAttributeMaxDynamicSharedMemorySize, attn_smem);

    convertW<<<128, 256>>>(Wq, Wk, Wv, Wo);
    qkv_gemm<<<dim3(3, 384), 256, GEMM_SMEM>>>(msa);
    attn16<<<S_DIM * NH, 384, attn_smem>>>();
    out_gemm<<<384, 256, GEMM_SMEM>>>(out);
}

// round 10
// speedup vs baseline: 1.0591x; 1.0591x over previous
#include <cuda_runtime.h>
#include <cuda_fp16.h>
#include <math.h>
#include <stdint.h>

#define S_DIM 128
#define L_DIM 384
#define DM 256
#define NH 8
#define HD 32
#define RTOT (S_DIM * L_DIM)           // 49152
#define ATT_SCALE_LOG2E 0.25501689767769175f  // (1/sqrt(32)) * log2(e)

// ---------------- scratch ----------------------------------------------------
__device__ __half g_x16[RTOT * DM];
__device__ __half g_wq16[DM * DM];
__device__ __half g_wk16[DM * DM];
__device__ __half g_wv16[DM * DM];
__device__ __half g_wo16[DM * DM];
__device__ __half g_q16[RTOT * DM];
__device__ __half g_k16[RTOT * DM];
__device__ __half g_v16[RTOT * DM];
__device__ __half g_ao16[RTOT * DM];

// ---------------- PTX helpers ------------------------------------------------
__device__ __forceinline__ void mma16816(float* d, const uint32_t* a, const uint32_t* b)
{
    asm volatile(
        "mma.sync.aligned.m16n8k16.row.col.f32.f16.f16.f32 "
        "{%0,%1,%2,%3}, {%4,%5,%6,%7}, {%8,%9}, {%0,%1,%2,%3};\n"
        : "+f"(d[0]), "+f"(d[1]), "+f"(d[2]), "+f"(d[3])
        : "r"(a[0]), "r"(a[1]), "r"(a[2]), "r"(a[3]), "r"(b[0]), "r"(b[1]));
}
__device__ __forceinline__ uint32_t s2u(const void* p)
{
    return (uint32_t)__cvta_generic_to_shared(p);
}
__device__ __forceinline__ void ldsm4(uint32_t* r, uint32_t a)
{
    asm volatile("ldmatrix.sync.aligned.m8n8.x4.shared.b16 {%0,%1,%2,%3}, [%4];\n"
                 : "=r"(r[0]), "=r"(r[1]), "=r"(r[2]), "=r"(r[3]) : "r"(a));
}
__device__ __forceinline__ void ldsm4t(uint32_t* r, uint32_t a)
{
    asm volatile("ldmatrix.sync.aligned.m8n8.x4.trans.shared.b16 {%0,%1,%2,%3}, [%4];\n"
                 : "=r"(r[0]), "=r"(r[1]), "=r"(r[2]), "=r"(r[3]) : "r"(a));
}
__device__ __forceinline__ void cpa16(uint32_t dst, const void* src)
{
    asm volatile("cp.async.cg.shared.global [%0], [%1], 16;\n" :: "r"(dst), "l"(src));
}
#define CP_COMMIT asm volatile("cp.async.commit_group;\n" ::: "memory")
#define CP_WAIT0  asm volatile("cp.async.wait_group 0;\n" ::: "memory")

__device__ __forceinline__ uint32_t pack2(float a, float b)
{
    __half2 h = __floats2half2_rn(a, b);
    return *(uint32_t*)&h;
}

// ---------------- conversion (fp32 -> fp16): msa + 4 weights -----------------
__global__ __launch_bounds__(256) void convertAll(
    const float* __restrict__ msa,
    const float* __restrict__ wq, const float* __restrict__ wk,
    const float* __restrict__ wv, const float* __restrict__ wo)
{
    const int i = blockIdx.x * blockDim.x + threadIdx.x;
    const int stride = gridDim.x * blockDim.x;
    const int n2 = RTOT * DM / 2;
    const float2* m2 = (const float2*)msa;
    __half2* x2 = (__half2*)g_x16;
    for (int t = i; t < n2; t += stride) {
        float2 v = m2[t];
        x2[t] = __floats2half2_rn(v.x, v.y);
    }
    const int w2 = DM * DM / 2;
    for (int t = i; t < w2; t += stride) {
        float2 v;
        v = ((const float2*)wq)[t]; ((__half2*)g_wq16)[t] = __floats2half2_rn(v.x, v.y);
        v = ((const float2*)wk)[t]; ((__half2*)g_wk16)[t] = __floats2half2_rn(v.x, v.y);
        v = ((const float2*)wv)[t]; ((__half2*)g_wv16)[t] = __floats2half2_rn(v.x, v.y);
        v = ((const float2*)wo)[t]; ((__half2*)g_wo16)[t] = __floats2half2_rn(v.x, v.y);
    }
}

// ---------------- 64-deep chunk compute (warp 32x64) -------------------------
// As_/Bs_ are [128][72] tiles (row stride 72 halfs).
__device__ __forceinline__ void gemm_chunk64(
    const __half* __restrict__ As_, const __half* __restrict__ Bs_,
    float acc[2][8][4], int wm, int wn, int lane)
{
    const int ar = lane & 15;
    const int ac = (lane >> 4) * 8;
    const int br = (lane & 7) + ((lane & 16) >> 1);
    const int bc = lane & 8;
    #pragma unroll
    for (int ks = 0; ks < 4; ks++) {
        uint32_t af[2][4];
        ldsm4(af[0], s2u(As_ + (wm + ar) * 72 + ks * 16 + ac));
        ldsm4(af[1], s2u(As_ + (wm + 16 + ar) * 72 + ks * 16 + ac));
        #pragma unroll
        for (int ni = 0; ni < 4; ni++) {
            uint32_t bf[4];
            ldsm4(bf, s2u(Bs_ + (wn + ni * 16 + br) * 72 + ks * 16 + bc));
            mma16816(acc[0][2 * ni],     af[0], bf);
            mma16816(acc[0][2 * ni + 1], af[0], bf + 2);
            mma16816(acc[1][2 * ni],     af[1], bf);
            mma16816(acc[1][2 * ni + 1], af[1], bf + 2);
        }
    }
}

// ---------------- unified GEMM: resident A (full K), streamed B --------------
// CTA: 256 threads, tile 128x128, warp tile 32x64 (2x2 warp grid x 2 in M... 8 warps).
// A (128x256 halfs) resident in smem as 4 chunk-tiles of [128][72].
// B streamed: NW weights x 4 chunks through a 2-stage [128][72] ring.
// smem: A 4*9216 + B 2*9216 = 55296 halfs = 110592 B -> 2 CTA/SM.
// NW==3: A=g_x16, outputs g_q16/g_k16/g_v16 (fp16). NW==1: A=g_ao16, out fp32.
#define SM64 110592

template<int NW, bool OUTF>
__global__ __launch_bounds__(256, 2) void gemm64(float* __restrict__ outF)
{
    extern __shared__ __half dsm[];
    const __half* __restrict__ A = (NW == 3) ? g_x16 : g_ao16;
    const __half* Wlist[3];
    if (NW == 3) { Wlist[0] = g_wq16; Wlist[1] = g_wk16; Wlist[2] = g_wv16; }
    else         { Wlist[0] = g_wo16; Wlist[1] = g_wo16; Wlist[2] = g_wo16; }

    const int ct = blockIdx.x * 128;
    const int rt = blockIdx.y * 128;
    const int tid = threadIdx.x;
    const int lane = tid & 31;
    const int wid = tid >> 5;
    const int wm = (wid >> 1) * 32;
    const int wn = (wid & 1) * 64;
    const int row = tid >> 1;            // 0..127
    const int hs = (tid & 1) * 32;       // half-offset within 64-col chunk

    // ---- prologue: full A tile (16 cpa16/thread) + B chunk 0, one group ----
    #pragma unroll
    for (int c = 0; c < 4; c++)
        #pragma unroll
        for (int i = 0; i < 4; i++)
            cpa16(s2u(dsm + c * 9216 + row * 72 + hs + i * 8),
                  &A[(size_t)(rt + row) * DM + c * 64 + hs + i * 8]);

    auto cpB = [&](int j) {              // j = w*4 + c
        const __half* W = Wlist[j >> 2];
        __half* ws_ = dsm + 36864 + (j & 1) * 9216;
        const int c = j & 3;
        #pragma unroll
        for (int i = 0; i < 4; i++)
            cpa16(s2u(ws_ + row * 72 + hs + i * 8),
                  &W[(size_t)(ct + row) * DM + c * 64 + hs + i * 8]);
        CP_COMMIT;
    };
    cpB(0);                              // group: A + B0

    const int g = lane >> 2;
    const int q = lane & 3;
    float acc[2][8][4] = {};

    const int J = 4 * NW;
    #pragma unroll
    for (int j = 0; j < J; j++) {
        CP_WAIT0;                        // chunk j (and A on j=0) complete
        __syncthreads();                 // all warps done with buffer (j+1)&1
        if (j + 1 < J) cpB(j + 1);       // prefetch overlaps compute(j)
        gemm_chunk64(dsm + (j & 3) * 9216, dsm + 36864 + (j & 1) * 9216,
                     acc, wm, wn, lane);
        if ((j & 3) == 3) {
            // epilogue for weight w = j>>2 (overlapped by next B prefetch)
            const int w = j >> 2;
            if (!OUTF) {
                __half* outH = (w == 0) ? g_q16 : (w == 1) ? g_k16 : g_v16;
                #pragma unroll
                for (int mi = 0; mi < 2; mi++)
                    #pragma unroll
                    for (int ni = 0; ni < 8; ni++) {
                        int r = rt + wm + mi * 16 + g;
                        int cc = ct + wn + ni * 8 + q * 2;
                        *(__half2*)&outH[(size_t)r * DM + cc] =
                            __floats2half2_rn(acc[mi][ni][0], acc[mi][ni][1]);
                        *(__half2*)&outH[(size_t)(r + 8) * DM + cc] =
                            __floats2half2_rn(acc[mi][ni][2], acc[mi][ni][3]);
                    }
            } else {
                #pragma unroll
                for (int mi = 0; mi < 2; mi++)
                    #pragma unroll
                    for (int ni = 0; ni < 8; ni++) {
                        int r = rt + wm + mi * 16 + g;
                        int cc = ct + wn + ni * 8 + q * 2;
                        *(float2*)&outF[(size_t)r * DM + cc] =
                            make_float2(acc[mi][ni][0], acc[mi][ni][1]);
                        *(float2*)&outF[(size_t)(r + 8) * DM + cc] =
                            make_float2(acc[mi][ni][2], acc[mi][ni][3]);
                    }
            }
            if (j + 1 < J) {
                #pragma unroll
                for (int mi = 0; mi < 2; mi++)
                    #pragma unroll
                    for (int ni = 0; ni < 8; ni++)
                        #pragma unroll
                        for (int t = 0; t < 4; t++) acc[mi][ni][t] = 0.0f;
            }
        }
    }
}

// ---------------- attention (unchanged from round 7) --------------------------
__global__ __launch_bounds__(384) void attn16()
{
    extern __shared__ __half sh[];
    __half (*Qs)[40] = (__half(*)[40])sh;
    __half (*Ks)[40] = (__half(*)[40])(sh + 384 * 40);
    __half (*Vs)[40] = (__half(*)[40])(sh + 2 * 384 * 40);

    const int s = blockIdx.x >> 3;
    const int h = blockIdx.x & 7;
    const size_t base = (size_t)s * L_DIM;
    const int tid = threadIdx.x;
    const int lane = tid & 31;
    const int wid = tid >> 5;
    const int g = lane >> 2;
    const int q = lane & 3;
    const int wq = wid * 32;

    {
        const __half* qp = &g_q16[(base + tid) * DM + h * HD];
        const __half* kp = &g_k16[(base + tid) * DM + h * HD];
        const __half* vp = &g_v16[(base + tid) * DM + h * HD];
        #pragma unroll
        for (int u = 0; u < 4; u++) {
            cpa16(s2u(&Qs[tid][u * 8]), qp + u * 8);
            cpa16(s2u(&Ks[tid][u * 8]), kp + u * 8);
            cpa16(s2u(&Vs[tid][u * 8]), vp + u * 8);
        }
        CP_COMMIT;
    }
    CP_WAIT0;
    __syncthreads();

    const int ar = (lane & 15);
    const int ac = (lane >> 4) * 8;
    const int br = (lane & 7) + ((lane & 16) >> 1);
    const int bc = (lane & 8);
    const int tr = (lane & 15);
    const int tc = (lane >> 4) * 8;

    uint32_t qf[2][2][4];
    #pragma unroll
    for (int mi = 0; mi < 2; mi++)
        #pragma unroll
        for (int ks = 0; ks < 2; ks++)
            ldsm4(qf[mi][ks], s2u(&Qs[wq + mi * 16 + ar][ks * 16 + ac]));

    float oacc[2][4][4] = {};
    float lsum[2][2] = {};

    #pragma unroll
    for (int kt = 0; kt < L_DIM; kt += 64) {
        #pragma unroll
        for (int nip = 0; nip < 4; nip++) {
            const int kr = kt + nip * 16;
            uint32_t kf0[4], kf1[4], vf0[4], vf1[4];
            ldsm4(kf0, s2u(&Ks[kr + br][bc]));
            ldsm4(kf1, s2u(&Ks[kr + br][16 + bc]));
            ldsm4t(vf0, s2u(&Vs[kr + tr][tc]));
            ldsm4t(vf1, s2u(&Vs[kr + tr][16 + tc]));

            float sacc[2][2][4] = {};
            #pragma unroll
            for (int mi = 0; mi < 2; mi++) {
                #pragma unroll
                for (int ni = 0; ni < 2; ni++) {
                    mma16816(sacc[mi][ni], qf[mi][0], kf0 + 2 * ni);
                    mma16816(sacc[mi][ni], qf[mi][1], kf1 + 2 * ni);
                }
            }

            uint32_t pf[2][4];
            #pragma unroll
            for (int mi = 0; mi < 2; mi++)
                #pragma unroll
                for (int ni = 0; ni < 2; ni++) {
                    float p0 = exp2f(sacc[mi][ni][0] * ATT_SCALE_LOG2E);
                    float p1 = exp2f(sacc[mi][ni][1] * ATT_SCALE_LOG2E);
                    float p2 = exp2f(sacc[mi][ni][2] * ATT_SCALE_LOG2E);
                    float p3 = exp2f(sacc[mi][ni][3] * ATT_SCALE_LOG2E);
                    lsum[mi][0] += p0 + p1;
                    lsum[mi][1] += p2 + p3;
                    pf[mi][ni * 2 + 0] = pack2(p0, p1);
                    pf[mi][ni * 2 + 1] = pack2(p2, p3);
                }

            #pragma unroll
            for (int mi = 0; mi < 2; mi++) {
                mma16816(oacc[mi][0], pf[mi], vf0);
                mma16816(oacc[mi][1], pf[mi], vf0 + 2);
                mma16816(oacc[mi][2], pf[mi], vf1);
                mma16816(oacc[mi][3], pf[mi], vf1 + 2);
            }
        }
    }

    float inv[2][2];
    #pragma unroll
    for (int mi = 0; mi < 2; mi++)
        #pragma unroll
        for (int hi = 0; hi < 2; hi++) {
            float l = lsum[mi][hi];
            l += __shfl_xor_sync(0xffffffffu, l, 1);
            l += __shfl_xor_sync(0xffffffffu, l, 2);
            inv[mi][hi] = 1.0f / l;
        }

    #pragma unroll
    for (int mi = 0; mi < 2; mi++)
        #pragma unroll
        for (int ni = 0; ni < 4; ni++) {
            size_t row = base + wq + mi * 16 + g;
            int col = h * HD + ni * 8 + q * 2;
            *(__half2*)&g_ao16[row * DM + col] =
                __floats2half2_rn(oacc[mi][ni][0] * inv[mi][0],
                                  oacc[mi][ni][1] * inv[mi][0]);
            *(__half2*)&g_ao16[(row + 8) * DM + col] =
                __floats2half2_rn(oacc[mi][ni][2] * inv[mi][1],
                                  oacc[mi][ni][3] * inv[mi][1]);
        }
}

// ---------------- launch -----------------------------------------------------
extern "C" void kernel_launch(void* const* d_in, const int* in_sizes, int n_in,
                              void* d_out, int out_size)
{
    (void)in_sizes; (void)n_in; (void)out_size;
    const float* msa = (const float*)d_in[0];
    const float* Wq  = (const float*)d_in[2];
    const float* Wk  = (const float*)d_in[3];
    const float* Wv  = (const float*)d_in[4];
    const float* Wo  = (const float*)d_in[5];
    float* out = (float*)d_out;

    const int attn_smem = 3 * 384 * 40 * (int)sizeof(__half); // 92160
    cudaFuncSetAttribute(gemm64<3, false>,
                         cudaFuncAttributeMaxDynamicSharedMemorySize, SM64);
    cudaFuncSetAttribute(gemm64<1, true>,
                         cudaFuncAttributeMaxDynamicSharedMemorySize, SM64);
    cudaFuncSetAttribute(attn16, cudaFuncAttributeMaxDynamicSharedMemorySize, attn_smem);

    convertAll<<<1024, 256>>>(msa, Wq, Wk, Wv, Wo);
    gemm64<3, false><<<dim3(2, 384), 256, SM64>>>(nullptr);  // Q,K,V
    attn16<<<S_DIM * NH, 384, attn_smem>>>();
    gemm64<1, true><<<dim3(2, 384), 256, SM64>>>(out);       // out
}

// round 12
// speedup vs baseline: 1.2261x; 1.1577x over previous
#include <cuda_runtime.h>
#include <cuda_fp16.h>
#include <math.h>
#include <stdint.h>

#define S_DIM 128
#define L_DIM 384
#define DM 256
#define NH 8
#define HD 32
#define RTOT (S_DIM * L_DIM)           // 49152
#define ATT_SCALE_LOG2E 0.25501689767769175f  // (1/sqrt(32)) * log2(e)

// ---------------- scratch ----------------------------------------------------
__device__ __half g_x16[RTOT * DM];
__device__ __half g_wq16[DM * DM];
__device__ __half g_wk16[DM * DM];
__device__ __half g_wv16[DM * DM];
__device__ __half g_wo16[DM * DM];
__device__ __half g_q16[RTOT * DM];
__device__ __half g_k16[RTOT * DM];
__device__ __half g_v16[RTOT * DM];
__device__ __half g_ao16[RTOT * DM];

// ---------------- PTX helpers ------------------------------------------------
__device__ __forceinline__ void mma16816(float* d, const uint32_t* a, const uint32_t* b)
{
    asm volatile(
        "mma.sync.aligned.m16n8k16.row.col.f32.f16.f16.f32 "
        "{%0,%1,%2,%3}, {%4,%5,%6,%7}, {%8,%9}, {%0,%1,%2,%3};\n"
        : "+f"(d[0]), "+f"(d[1]), "+f"(d[2]), "+f"(d[3])
        : "r"(a[0]), "r"(a[1]), "r"(a[2]), "r"(a[3]), "r"(b[0]), "r"(b[1]));
}
__device__ __forceinline__ uint32_t s2u(const void* p)
{
    return (uint32_t)__cvta_generic_to_shared(p);
}
__device__ __forceinline__ void ldsm4(uint32_t* r, uint32_t a)
{
    asm volatile("ldmatrix.sync.aligned.m8n8.x4.shared.b16 {%0,%1,%2,%3}, [%4];\n"
                 : "=r"(r[0]), "=r"(r[1]), "=r"(r[2]), "=r"(r[3]) : "r"(a));
}
__device__ __forceinline__ void ldsm4t(uint32_t* r, uint32_t a)
{
    asm volatile("ldmatrix.sync.aligned.m8n8.x4.trans.shared.b16 {%0,%1,%2,%3}, [%4];\n"
                 : "=r"(r[0]), "=r"(r[1]), "=r"(r[2]), "=r"(r[3]) : "r"(a));
}
__device__ __forceinline__ void cpa16(uint32_t dst, const void* src)
{
    asm volatile("cp.async.cg.shared.global [%0], [%1], 16;\n" :: "r"(dst), "l"(src));
}
#define CP_COMMIT asm volatile("cp.async.commit_group;\n" ::: "memory")
#define CP_WAIT0  asm volatile("cp.async.wait_group 0;\n" ::: "memory")
#define CP_WAIT1  asm volatile("cp.async.wait_group 1;\n" ::: "memory")
#define CP_WAIT2  asm volatile("cp.async.wait_group 2;\n" ::: "memory")

__device__ __forceinline__ uint32_t pack2(float a, float b)
{
    __half2 h = __floats2half2_rn(a, b);
    return *(uint32_t*)&h;
}
// raw MUFU exp2 — one EX2 op, no libdevice wrapper
__device__ __forceinline__ float ex2(float x)
{
    float r;
    asm("ex2.approx.ftz.f32 %0, %1;" : "=f"(r) : "f"(x));
    return r;
}

// ---------------- conversion (fp32 -> fp16): msa + 4 weights -----------------
__global__ __launch_bounds__(256) void convertAll(
    const float* __restrict__ msa,
    const float* __restrict__ wq, const float* __restrict__ wk,
    const float* __restrict__ wv, const float* __restrict__ wo)
{
    const int i = blockIdx.x * blockDim.x + threadIdx.x;
    const int stride = gridDim.x * blockDim.x;
    const int n2 = RTOT * DM / 2;
    const float2* m2 = (const float2*)msa;
    __half2* x2 = (__half2*)g_x16;
    for (int t = i; t < n2; t += stride) {
        float2 v = m2[t];
        x2[t] = __floats2half2_rn(v.x, v.y);
    }
    const int w2 = DM * DM / 2;
    for (int t = i; t < w2; t += stride) {
        float2 v;
        v = ((const float2*)wq)[t]; ((__half2*)g_wq16)[t] = __floats2half2_rn(v.x, v.y);
        v = ((const float2*)wk)[t]; ((__half2*)g_wk16)[t] = __floats2half2_rn(v.x, v.y);
        v = ((const float2*)wv)[t]; ((__half2*)g_wv16)[t] = __floats2half2_rn(v.x, v.y);
        v = ((const float2*)wo)[t]; ((__half2*)g_wo16)[t] = __floats2half2_rn(v.x, v.y);
    }
}

// ---------------- per-chunk tensor compute (32 k-depth, frag-pipelined) ------
__device__ __forceinline__ void gemm_chunk(
    const __half* __restrict__ As, const __half* __restrict__ Ws,
    float acc[2][8][4], int wm, int wn, int lane)
{
    const int ar = (lane & 15);
    const int ac = (lane >> 4) * 8;
    const int br = (lane & 7) + ((lane & 16) >> 1);
    const int bc = (lane & 8);

    uint32_t af[2][2][4];           // [ks][mi]
    ldsm4(af[0][0], s2u(As + (wm + ar) * 40 + ac));
    ldsm4(af[0][1], s2u(As + (wm + 16 + ar) * 40 + ac));
    ldsm4(af[1][0], s2u(As + (wm + ar) * 40 + 16 + ac));
    ldsm4(af[1][1], s2u(As + (wm + 16 + ar) * 40 + 16 + ac));

    uint32_t bfd[2][4];             // B double buffer
    ldsm4(bfd[0], s2u(Ws + (wn + br) * 40 + bc));

    #pragma unroll
    for (int j = 0; j < 8; j++) {   // j = ks*4 + nip
        const int ks = j >> 2, nip = j & 3;
        const int cur = j & 1;
        if (j < 7) {
            const int jn = j + 1;
            ldsm4(bfd[cur ^ 1],
                  s2u(Ws + (wn + (jn & 3) * 16 + br) * 40 + (jn >> 2) * 16 + bc));
        }
        mma16816(acc[0][2 * nip],     af[ks][0], bfd[cur]);
        mma16816(acc[0][2 * nip + 1], af[ks][0], bfd[cur] + 2);
        mma16816(acc[1][2 * nip],     af[ks][1], bfd[cur]);
        mma16816(acc[1][2 * nip + 1], af[ks][1], bfd[cur] + 2);
    }
}

// ---------------- 4-stage pipelined mainloop ---------------------------------
__device__ __forceinline__ void gemm_core(
    const __half* __restrict__ A, const __half* __restrict__ W,
    __half* dsm, int rt, int ct, float acc[2][8][4])
{
    const int tid = threadIdx.x;
    const int lane = tid & 31;
    const int wid = tid >> 5;
    const int wm = (wid >> 1) * 32;
    const int wn = (wid & 1) * 64;
    const int r0 = tid >> 2;
    const int s0 = (tid & 3) * 8;
    const int r1 = r0 + 64;

    #define CP_CHUNK(kc, buf)                                                          \
        do {                                                                           \
            __half* as_ = dsm + (buf) * 5120;                                          \
            __half* ws_ = dsm + 20480 + (buf) * 5120;                                  \
            cpa16(s2u(as_ + r0 * 40 + s0), &A[(size_t)(rt + r0) * DM + (kc) + s0]);    \
            cpa16(s2u(as_ + r1 * 40 + s0), &A[(size_t)(rt + r1) * DM + (kc) + s0]);    \
            cpa16(s2u(ws_ + r0 * 40 + s0), &W[(size_t)(ct + r0) * DM + (kc) + s0]);    \
            cpa16(s2u(ws_ + r1 * 40 + s0), &W[(size_t)(ct + r1) * DM + (kc) + s0]);    \
            CP_COMMIT;                                                                 \
        } while (0)

    CP_CHUNK(0, 0);
    CP_CHUNK(32, 1);
    CP_CHUNK(64, 2);

    #pragma unroll
    for (int kc = 0; kc < 8; kc++) {
        const int buf = kc & 3;
        if (kc < 6) { CP_WAIT2; } else if (kc == 6) { CP_WAIT1; } else { CP_WAIT0; }
        __syncthreads();
        if (kc + 3 < 8) CP_CHUNK((kc + 3) * 32, (kc + 3) & 3);
        gemm_chunk(dsm + buf * 5120, dsm + 20480 + buf * 5120, acc, wm, wn, lane);
    }
    #undef CP_CHUNK
}

// ---------------- fused QKV GEMM (all fp16) ----------------------------------
__global__ __launch_bounds__(256, 2) void qkv_gemm()
{
    extern __shared__ __half dsm[];

    const int wIdx = blockIdx.x >> 1;
    const int ct = (blockIdx.x & 1) * 128;
    const int rt = blockIdx.y * 128;
    const __half* __restrict__ W =
        (wIdx == 0) ? g_wq16 : (wIdx == 1) ? g_wk16 : g_wv16;
    __half* __restrict__ outH =
        (wIdx == 0) ? g_q16 : (wIdx == 1) ? g_k16 : g_v16;

    float acc[2][8][4] = {};
    gemm_core(g_x16, W, dsm, rt, ct, acc);

    const int lane = threadIdx.x & 31;
    const int wid = threadIdx.x >> 5;
    const int wm = (wid >> 1) * 32;
    const int wn = (wid & 1) * 64;
    const int g = lane >> 2;
    const int q = lane & 3;
    #pragma unroll
    for (int mi = 0; mi < 2; mi++)
        #pragma unroll
        for (int ni = 0; ni < 8; ni++) {
            int row = rt + wm + mi * 16 + g;
            int col = ct + wn + ni * 8 + q * 2;
            *(__half2*)&outH[(size_t)row * DM + col] =
                __floats2half2_rn(acc[mi][ni][0], acc[mi][ni][1]);
            *(__half2*)&outH[(size_t)(row + 8) * DM + col] =
                __floats2half2_rn(acc[mi][ni][2], acc[mi][ni][3]);
        }
}

// ---------------- output GEMM ------------------------------------------------
__global__ __launch_bounds__(256, 2) void out_gemm(float* __restrict__ outF)
{
    extern __shared__ __half dsm[];

    const int ct = blockIdx.x * 128;
    const int rt = blockIdx.y * 128;

    float acc[2][8][4] = {};
    gemm_core(g_ao16, g_wo16, dsm, rt, ct, acc);

    const int lane = threadIdx.x & 31;
    const int wid = threadIdx.x >> 5;
    const int wm = (wid >> 1) * 32;
    const int wn = (wid & 1) * 64;
    const int g = lane >> 2;
    const int q = lane & 3;
    #pragma unroll
    for (int mi = 0; mi < 2; mi++)
        #pragma unroll
        for (int ni = 0; ni < 8; ni++) {
            int row = rt + wm + mi * 16 + g;
            int col = ct + wn + ni * 8 + q * 2;
            *(float2*)&outF[(size_t)row * DM + col] =
                make_float2(acc[mi][ni][0], acc[mi][ni][1]);
            *(float2*)&outF[(size_t)(row + 8) * DM + col] =
                make_float2(acc[mi][ni][2], acc[mi][ni][3]);
        }
}

// ---------------- attention --------------------------------------------------
// block = (s,h); 12 warps x 32 query rows. Per 16-key group: QK mma -> raw-MUFU
// exp -> PV mma interleaved.
__global__ __launch_bounds__(384) void attn16()
{
    extern __shared__ __half sh[];
    __half (*Qs)[40] = (__half(*)[40])sh;
    __half (*Ks)[40] = (__half(*)[40])(sh + 384 * 40);
    __half (*Vs)[40] = (__half(*)[40])(sh + 2 * 384 * 40);

    const int s = blockIdx.x >> 3;
    const int h = blockIdx.x & 7;
    const size_t base = (size_t)s * L_DIM;
    const int tid = threadIdx.x;
    const int lane = tid & 31;
    const int wid = tid >> 5;
    const int g = lane >> 2;
    const int q = lane & 3;
    const int wq = wid * 32;

    {
        const __half* qp = &g_q16[(base + tid) * DM + h * HD];
        const __half* kp = &g_k16[(base + tid) * DM + h * HD];
        const __half* vp = &g_v16[(base + tid) * DM + h * HD];
        #pragma unroll
        for (int u = 0; u < 4; u++) {
            cpa16(s2u(&Qs[tid][u * 8]), qp + u * 8);
            cpa16(s2u(&Ks[tid][u * 8]), kp + u * 8);
            cpa16(s2u(&Vs[tid][u * 8]), vp + u * 8);
        }
        CP_COMMIT;
    }
    CP_WAIT0;
    __syncthreads();

    const int ar = (lane & 15);
    const int ac = (lane >> 4) * 8;
    const int br = (lane & 7) + ((lane & 16) >> 1);
    const int bc = (lane & 8);
    const int tr = (lane & 15);
    const int tc = (lane >> 4) * 8;

    uint32_t qf[2][2][4];
    #pragma unroll
    for (int mi = 0; mi < 2; mi++)
        #pragma unroll
        for (int ks = 0; ks < 2; ks++)
            ldsm4(qf[mi][ks], s2u(&Qs[wq + mi * 16 + ar][ks * 16 + ac]));

    float oacc[2][4][4] = {};
    float lsum[2][2] = {};

    #pragma unroll
    for (int kt = 0; kt < L_DIM; kt += 64) {
        #pragma unroll
        for (int nip = 0; nip < 4; nip++) {
            const int kr = kt + nip * 16;
            uint32_t kf0[4], kf1[4], vf0[4], vf1[4];
            ldsm4(kf0, s2u(&Ks[kr + br][bc]));
            ldsm4(kf1, s2u(&Ks[kr + br][16 + bc]));
            ldsm4t(vf0, s2u(&Vs[kr + tr][tc]));
            ldsm4t(vf1, s2u(&Vs[kr + tr][16 + tc]));

            float sacc[2][2][4] = {};
            #pragma unroll
            for (int mi = 0; mi < 2; mi++) {
                #pragma unroll
                for (int ni = 0; ni < 2; ni++) {
                    mma16816(sacc[mi][ni], qf[mi][0], kf0 + 2 * ni);
                    mma16816(sacc[mi][ni], qf[mi][1], kf1 + 2 * ni);
                }
            }

            uint32_t pf[2][4];
            #pragma unroll
            for (int mi = 0; mi < 2; mi++)
                #pragma unroll
                for (int ni = 0; ni < 2; ni++) {
                    float p0 = ex2(sacc[mi][ni][0] * ATT_SCALE_LOG2E);
                    float p1 = ex2(sacc[mi][ni][1] * ATT_SCALE_LOG2E);
                    float p2 = ex2(sacc[mi][ni][2] * ATT_SCALE_LOG2E);
                    float p3 = ex2(sacc[mi][ni][3] * ATT_SCALE_LOG2E);
                    lsum[mi][0] += p0 + p1;
                    lsum[mi][1] += p2 + p3;
                    pf[mi][ni * 2 + 0] = pack2(p0, p1);
                    pf[mi][ni * 2 + 1] = pack2(p2, p3);
                }

            #pragma unroll
            for (int mi = 0; mi < 2; mi++) {
                mma16816(oacc[mi][0], pf[mi], vf0);
                mma16816(oacc[mi][1], pf[mi], vf0 + 2);
                mma16816(oacc[mi][2], pf[mi], vf1);
                mma16816(oacc[mi][3], pf[mi], vf1 + 2);
            }
        }
    }

    float inv[2][2];
    #pragma unroll
    for (int mi = 0; mi < 2; mi++)
        #pragma unroll
        for (int hi = 0; hi < 2; hi++) {
            float l = lsum[mi][hi];
            l += __shfl_xor_sync(0xffffffffu, l, 1);
            l += __shfl_xor_sync(0xffffffffu, l, 2);
            inv[mi][hi] = 1.0f / l;
        }

    #pragma unroll
    for (int mi = 0; mi < 2; mi++)
        #pragma unroll
        for (int ni = 0; ni < 4; ni++) {
            size_t row = base + wq + mi * 16 + g;
            int col = h * HD + ni * 8 + q * 2;
            *(__half2*)&g_ao16[row * DM + col] =
                __floats2half2_rn(oacc[mi][ni][0] * inv[mi][0],
                                  oacc[mi][ni][1] * inv[mi][0]);
            *(__half2*)&g_ao16[(row + 8) * DM + col] =
                __floats2half2_rn(oacc[mi][ni][2] * inv[mi][1],
                                  oacc[mi][ni][3] * inv[mi][1]);
        }
}

// ---------------- launch -----------------------------------------------------
extern "C" void kernel_launch(void* const* d_in, const int* in_sizes, int n_in,
                              void* d_out, int out_size)
{
    (void)in_sizes; (void)n_in; (void)out_size;
    const float* msa = (const float*)d_in[0];
    const float* Wq  = (const float*)d_in[2];
    const float* Wk  = (const float*)d_in[3];
    const float* Wv  = (const float*)d_in[4];
    const float* Wo  = (const float*)d_in[5];
    float* out = (float*)d_out;

    const int gemm_smem = 2 * 4 * 128 * 40 * (int)sizeof(__half); // 81920
    const int attn_smem = 3 * 384 * 40 * (int)sizeof(__half);     // 92160
    cudaFuncSetAttribute(qkv_gemm, cudaFuncAttributeMaxDynamicSharedMemorySize, gemm_smem);
    cudaFuncSetAttribute(out_gemm, cudaFuncAttributeMaxDynamicSharedMemorySize, gemm_smem);
    cudaFuncSetAttribute(attn16,   cudaFuncAttributeMaxDynamicSharedMemorySize, attn_smem);

    convertAll<<<1024, 256>>>(msa, Wq, Wk, Wv, Wo);
    qkv_gemm<<<dim3(6, 384), 256, gemm_smem>>>();
    attn16<<<S_DIM * NH, 384, attn_smem>>>();
    out_gemm<<<dim3(2, 384), 256, gemm_smem>>>(out);
}

// round 13
// speedup vs baseline: 1.2379x; 1.0096x over previous
#include <cuda_runtime.h>
#include <cuda_fp16.h>
#include <math.h>
#include <stdint.h>

#define S_DIM 128
#define L_DIM 384
#define DM 256
#define NH 8
#define HD 32
#define RTOT (S_DIM * L_DIM)           // 49152
#define ATT_SCALE_LOG2E 0.25501689767769175f  // (1/sqrt(32)) * log2(e)

// ---------------- scratch ----------------------------------------------------
__device__ __half g_x16[RTOT * DM];
__device__ __half g_wq16[DM * DM];
__device__ __half g_wk16[DM * DM];
__device__ __half g_wv16[DM * DM];
__device__ __half g_wo16[DM * DM];
__device__ __half g_q16[RTOT * DM];
__device__ __half g_k16[RTOT * DM];
__device__ __half g_v16[RTOT * DM];
__device__ __half g_ao16[RTOT * DM];

// ---------------- PTX helpers ------------------------------------------------
__device__ __forceinline__ void mma16816(float* d, const uint32_t* a, const uint32_t* b)
{
    asm volatile(
        "mma.sync.aligned.m16n8k16.row.col.f32.f16.f16.f32 "
        "{%0,%1,%2,%3}, {%4,%5,%6,%7}, {%8,%9}, {%0,%1,%2,%3};\n"
        : "+f"(d[0]), "+f"(d[1]), "+f"(d[2]), "+f"(d[3])
        : "r"(a[0]), "r"(a[1]), "r"(a[2]), "r"(a[3]), "r"(b[0]), "r"(b[1]));
}
__device__ __forceinline__ uint32_t s2u(const void* p)
{
    return (uint32_t)__cvta_generic_to_shared(p);
}
__device__ __forceinline__ void ldsm4(uint32_t* r, uint32_t a)
{
    asm volatile("ldmatrix.sync.aligned.m8n8.x4.shared.b16 {%0,%1,%2,%3}, [%4];\n"
                 : "=r"(r[0]), "=r"(r[1]), "=r"(r[2]), "=r"(r[3]) : "r"(a));
}
__device__ __forceinline__ void ldsm4t(uint32_t* r, uint32_t a)
{
    asm volatile("ldmatrix.sync.aligned.m8n8.x4.trans.shared.b16 {%0,%1,%2,%3}, [%4];\n"
                 : "=r"(r[0]), "=r"(r[1]), "=r"(r[2]), "=r"(r[3]) : "r"(a));
}
__device__ __forceinline__ void cpa16(uint32_t dst, const void* src)
{
    asm volatile("cp.async.cg.shared.global [%0], [%1], 16;\n" :: "r"(dst), "l"(src));
}
#define CP_COMMIT asm volatile("cp.async.commit_group;\n" ::: "memory")
#define CP_WAIT0  asm volatile("cp.async.wait_group 0;\n" ::: "memory")
#define CP_WAIT1  asm volatile("cp.async.wait_group 1;\n" ::: "memory")
#define CP_WAIT2  asm volatile("cp.async.wait_group 2;\n" ::: "memory")

__device__ __forceinline__ uint32_t pack2(float a, float b)
{
    __half2 h = __floats2half2_rn(a, b);
    return *(uint32_t*)&h;
}
// pack two f32 into f16x2 (lo = a, hi = b)
__device__ __forceinline__ uint32_t cvt_f16x2(float a, float b)
{
    uint32_t d;
    asm("cvt.rn.f16x2.f32 %0, %1, %2;" : "=r"(d) : "f"(b), "f"(a));
    return d;
}
// two exp2's in one MUFU op
__device__ __forceinline__ uint32_t ex2_h2(uint32_t x)
{
    uint32_t d;
    asm("ex2.approx.f16x2 %0, %1;" : "=r"(d) : "r"(x));
    return d;
}

// ---------------- conversion (fp32 -> fp16): msa + 4 weights -----------------
__global__ __launch_bounds__(256) void convertAll(
    const float* __restrict__ msa,
    const float* __restrict__ wq, const float* __restrict__ wk,
    const float* __restrict__ wv, const float* __restrict__ wo)
{
    const int i = blockIdx.x * blockDim.x + threadIdx.x;
    const int stride = gridDim.x * blockDim.x;
    const int n2 = RTOT * DM / 2;
    const float2* m2 = (const float2*)msa;
    __half2* x2 = (__half2*)g_x16;
    for (int t = i; t < n2; t += stride) {
        float2 v = m2[t];
        x2[t] = __floats2half2_rn(v.x, v.y);
    }
    const int w2 = DM * DM / 2;
    for (int t = i; t < w2; t += stride) {
        float2 v;
        v = ((const float2*)wq)[t]; ((__half2*)g_wq16)[t] = __floats2half2_rn(v.x, v.y);
        v = ((const float2*)wk)[t]; ((__half2*)g_wk16)[t] = __floats2half2_rn(v.x, v.y);
        v = ((const float2*)wv)[t]; ((__half2*)g_wv16)[t] = __floats2half2_rn(v.x, v.y);
        v = ((const float2*)wo)[t]; ((__half2*)g_wo16)[t] = __floats2half2_rn(v.x, v.y);
    }
}

// ---------------- per-chunk tensor compute (32 k-depth, frag-pipelined) ------
__device__ __forceinline__ void gemm_chunk(
    const __half* __restrict__ As, const __half* __restrict__ Ws,
    float acc[2][8][4], int wm, int wn, int lane)
{
    const int ar = (lane & 15);
    const int ac = (lane >> 4) * 8;
    const int br = (lane & 7) + ((lane & 16) >> 1);
    const int bc = (lane & 8);

    uint32_t af[2][2][4];           // [ks][mi]
    ldsm4(af[0][0], s2u(As + (wm + ar) * 40 + ac));
    ldsm4(af[0][1], s2u(As + (wm + 16 + ar) * 40 + ac));
    ldsm4(af[1][0], s2u(As + (wm + ar) * 40 + 16 + ac));
    ldsm4(af[1][1], s2u(As + (wm + 16 + ar) * 40 + 16 + ac));

    uint32_t bfd[2][4];             // B double buffer
    ldsm4(bfd[0], s2u(Ws + (wn + br) * 40 + bc));

    #pragma unroll
    for (int j = 0; j < 8; j++) {   // j = ks*4 + nip
        const int ks = j >> 2, nip = j & 3;
        const int cur = j & 1;
        if (j < 7) {
            const int jn = j + 1;
            ldsm4(bfd[cur ^ 1],
                  s2u(Ws + (wn + (jn & 3) * 16 + br) * 40 + (jn >> 2) * 16 + bc));
        }
        mma16816(acc[0][2 * nip],     af[ks][0], bfd[cur]);
        mma16816(acc[0][2 * nip + 1], af[ks][0], bfd[cur] + 2);
        mma16816(acc[1][2 * nip],     af[ks][1], bfd[cur]);
        mma16816(acc[1][2 * nip + 1], af[ks][1], bfd[cur] + 2);
    }
}

// ---------------- 4-stage pipelined mainloop ---------------------------------
__device__ __forceinline__ void gemm_core(
    const __half* __restrict__ A, const __half* __restrict__ W,
    __half* dsm, int rt, int ct, float acc[2][8][4])
{
    const int tid = threadIdx.x;
    const int lane = tid & 31;
    const int wid = tid >> 5;
    const int wm = (wid >> 1) * 32;
    const int wn = (wid & 1) * 64;
    const int r0 = tid >> 2;
    const int s0 = (tid & 3) * 8;
    const int r1 = r0 + 64;

    #define CP_CHUNK(kc, buf)                                                          \
        do {                                                                           \
            __half* as_ = dsm + (buf) * 5120;                                          \
            __half* ws_ = dsm + 20480 + (buf) * 5120;                                  \
            cpa16(s2u(as_ + r0 * 40 + s0), &A[(size_t)(rt + r0) * DM + (kc) + s0]);    \
            cpa16(s2u(as_ + r1 * 40 + s0), &A[(size_t)(rt + r1) * DM + (kc) + s0]);    \
            cpa16(s2u(ws_ + r0 * 40 + s0), &W[(size_t)(ct + r0) * DM + (kc) + s0]);    \
            cpa16(s2u(ws_ + r1 * 40 + s0), &W[(size_t)(ct + r1) * DM + (kc) + s0]);    \
            CP_COMMIT;                                                                 \
        } while (0)

    CP_CHUNK(0, 0);
    CP_CHUNK(32, 1);
    CP_CHUNK(64, 2);

    #pragma unroll
    for (int kc = 0; kc < 8; kc++) {
        const int buf = kc & 3;
        if (kc < 6) { CP_WAIT2; } else if (kc == 6) { CP_WAIT1; } else { CP_WAIT0; }
        __syncthreads();
        if (kc + 3 < 8) CP_CHUNK((kc + 3) * 32, (kc + 3) & 3);
        gemm_chunk(dsm + buf * 5120, dsm + 20480 + buf * 5120, acc, wm, wn, lane);
    }
    #undef CP_CHUNK
}

// ---------------- fused QKV GEMM (all fp16) ----------------------------------
__global__ __launch_bounds__(256, 2) void qkv_gemm()
{
    extern __shared__ __half dsm[];

    const int wIdx = blockIdx.x >> 1;
    const int ct = (blockIdx.x & 1) * 128;
    const int rt = blockIdx.y * 128;
    const __half* __restrict__ W =
        (wIdx == 0) ? g_wq16 : (wIdx == 1) ? g_wk16 : g_wv16;
    __half* __restrict__ outH =
        (wIdx == 0) ? g_q16 : (wIdx == 1) ? g_k16 : g_v16;

    float acc[2][8][4] = {};
    gemm_core(g_x16, W, dsm, rt, ct, acc);

    const int lane = threadIdx.x & 31;
    const int wid = threadIdx.x >> 5;
    const int wm = (wid >> 1) * 32;
    const int wn = (wid & 1) * 64;
    const int g = lane >> 2;
    const int q = lane & 3;
    #pragma unroll
    for (int mi = 0; mi < 2; mi++)
        #pragma unroll
        for (int ni = 0; ni < 8; ni++) {
            int row = rt + wm + mi * 16 + g;
            int col = ct + wn + ni * 8 + q * 2;
            *(__half2*)&outH[(size_t)row * DM + col] =
                __floats2half2_rn(acc[mi][ni][0], acc[mi][ni][1]);
            *(__half2*)&outH[(size_t)(row + 8) * DM + col] =
                __floats2half2_rn(acc[mi][ni][2], acc[mi][ni][3]);
        }
}

// ---------------- output GEMM ------------------------------------------------
__global__ __launch_bounds__(256, 2) void out_gemm(float* __restrict__ outF)
{
    extern __shared__ __half dsm[];

    const int ct = blockIdx.x * 128;
    const int rt = blockIdx.y * 128;

    float acc[2][8][4] = {};
    gemm_core(g_ao16, g_wo16, dsm, rt, ct, acc);

    const int lane = threadIdx.x & 31;
    const int wid = threadIdx.x >> 5;
    const int wm = (wid >> 1) * 32;
    const int wn = (wid & 1) * 64;
    const int g = lane >> 2;
    const int q = lane & 3;
    #pragma unroll
    for (int mi = 0; mi < 2; mi++)
        #pragma unroll
        for (int ni = 0; ni < 8; ni++) {
            int row = rt + wm + mi * 16 + g;
            int col = ct + wn + ni * 8 + q * 2;
            *(float2*)&outF[(size_t)row * DM + col] =
                make_float2(acc[mi][ni][0], acc[mi][ni][1]);
            *(float2*)&outF[(size_t)(row + 8) * DM + col] =
                make_float2(acc[mi][ni][2], acc[mi][ni][3]);
        }
}

// ---------------- attention --------------------------------------------------
// block = (s,h); 12 warps x 32 query rows. Per 16-key group: QK mma ->
// f16x2 exp (half the MUFU ops) -> PV mma; row-sums accumulated on the tensor
// pipe via an extra mma against a ones B-fragment.
__global__ __launch_bounds__(384) void attn16()
{
    extern __shared__ __half sh[];
    __half (*Qs)[40] = (__half(*)[40])sh;
    __half (*Ks)[40] = (__half(*)[40])(sh + 384 * 40);
    __half (*Vs)[40] = (__half(*)[40])(sh + 2 * 384 * 40);

    const int s = blockIdx.x >> 3;
    const int h = blockIdx.x & 7;
    const size_t base = (size_t)s * L_DIM;
    const int tid = threadIdx.x;
    const int lane = tid & 31;
    const int wid = tid >> 5;
    const int g = lane >> 2;
    const int q = lane & 3;
    const int wq = wid * 32;

    {
        const __half* qp = &g_q16[(base + tid) * DM + h * HD];
        const __half* kp = &g_k16[(base + tid) * DM + h * HD];
        const __half* vp = &g_v16[(base + tid) * DM + h * HD];
        #pragma unroll
        for (int u = 0; u < 4; u++) {
            cpa16(s2u(&Qs[tid][u * 8]), qp + u * 8);
            cpa16(s2u(&Ks[tid][u * 8]), kp + u * 8);
            cpa16(s2u(&Vs[tid][u * 8]), vp + u * 8);
        }
        CP_COMMIT;
    }
    CP_WAIT0;
    __syncthreads();

    const int ar = (lane & 15);
    const int ac = (lane >> 4) * 8;
    const int br = (lane & 7) + ((lane & 16) >> 1);
    const int bc = (lane & 8);
    const int tr = (lane & 15);
    const int tc = (lane >> 4) * 8;

    uint32_t qf[2][2][4];
    #pragma unroll
    for (int mi = 0; mi < 2; mi++)
        #pragma unroll
        for (int ks = 0; ks < 2; ks++)
            ldsm4(qf[mi][ks], s2u(&Qs[wq + mi * 16 + ar][ks * 16 + ac]));

    const uint32_t ones2[2] = { 0x3C003C00u, 0x3C003C00u };  // ones B-fragment
    float oacc[2][4][4] = {};
    float lsacc[2][4] = {};          // row sums via mma (d0=row g, d2=row g+8)

    #pragma unroll
    for (int kt = 0; kt < L_DIM; kt += 64) {
        #pragma unroll
        for (int nip = 0; nip < 4; nip++) {
            const int kr = kt + nip * 16;
            uint32_t kf0[4], kf1[4], vf0[4], vf1[4];
            ldsm4(kf0, s2u(&Ks[kr + br][bc]));
            ldsm4(kf1, s2u(&Ks[kr + br][16 + bc]));
            ldsm4t(vf0, s2u(&Vs[kr + tr][tc]));
            ldsm4t(vf1, s2u(&Vs[kr + tr][16 + tc]));

            float sacc[2][2][4] = {};
            #pragma unroll
            for (int mi = 0; mi < 2; mi++) {
                #pragma unroll
                for (int ni = 0; ni < 2; ni++) {
                    mma16816(sacc[mi][ni], qf[mi][0], kf0 + 2 * ni);
                    mma16816(sacc[mi][ni], qf[mi][1], kf1 + 2 * ni);
                }
            }

            uint32_t pf[2][4];
            #pragma unroll
            for (int mi = 0; mi < 2; mi++)
                #pragma unroll
                for (int ni = 0; ni < 2; ni++) {
                    float t0 = sacc[mi][ni][0] * ATT_SCALE_LOG2E;
                    float t1 = sacc[mi][ni][1] * ATT_SCALE_LOG2E;
                    float t2 = sacc[mi][ni][2] * ATT_SCALE_LOG2E;
                    float t3 = sacc[mi][ni][3] * ATT_SCALE_LOG2E;
                    pf[mi][ni * 2 + 0] = ex2_h2(cvt_f16x2(t0, t1));
                    pf[mi][ni * 2 + 1] = ex2_h2(cvt_f16x2(t2, t3));
                }

            #pragma unroll
            for (int mi = 0; mi < 2; mi++) {
                mma16816(lsacc[mi], pf[mi], ones2);   // row sums on tensor pipe
                mma16816(oacc[mi][0], pf[mi], vf0);
                mma16816(oacc[mi][1], pf[mi], vf0 + 2);
                mma16816(oacc[mi][2], pf[mi], vf1);
                mma16816(oacc[mi][3], pf[mi], vf1 + 2);
            }
        }
    }

    // lsacc[mi][0] = sum for row g; lsacc[mi][2] = sum for row g+8 (all cols equal)
    float inv[2][2];
    #pragma unroll
    for (int mi = 0; mi < 2; mi++) {
        inv[mi][0] = 1.0f / lsacc[mi][0];
        inv[mi][1] = 1.0f / lsacc[mi][2];
    }

    #pragma unroll
    for (int mi = 0; mi < 2; mi++)
        #pragma unroll
        for (int ni = 0; ni < 4; ni++) {
            size_t row = base + wq + mi * 16 + g;
            int col = h * HD + ni * 8 + q * 2;
            *(__half2*)&g_ao16[row * DM + col] =
                __floats2half2_rn(oacc[mi][ni][0] * inv[mi][0],
                                  oacc[mi][ni][1] * inv[mi][0]);
            *(__half2*)&g_ao16[(row + 8) * DM + col] =
                __floats2half2_rn(oacc[mi][ni][2] * inv[mi][1],
                                  oacc[mi][ni][3] * inv[mi][1]);
        }
}

// ---------------- launch -----------------------------------------------------
extern "C" void kernel_launch(void* const* d_in, const int* in_sizes, int n_in,
                              void* d_out, int out_size)
{
    (void)in_sizes; (void)n_in; (void)out_size;
    const float* msa = (const float*)d_in[0];
    const float* Wq  = (const float*)d_in[2];
    const float* Wk  = (const float*)d_in[3];
    const float* Wv  = (const float*)d_in[4];
    const float* Wo  = (const float*)d_in[5];
    float* out = (float*)d_out;

    const int gemm_smem = 2 * 4 * 128 * 40 * (int)sizeof(__half); // 81920
    const int attn_smem = 3 * 384 * 40 * (int)sizeof(__half);     // 92160
    cudaFuncSetAttribute(qkv_gemm, cudaFuncAttributeMaxDynamicSharedMemorySize, gemm_smem);
    cudaFuncSetAttribute(out_gemm, cudaFuncAttributeMaxDynamicSharedMemorySize, gemm_smem);
    cudaFuncSetAttribute(attn16,   cudaFuncAttributeMaxDynamicSharedMemorySize, attn_smem);

    convertAll<<<1024, 256>>>(msa, Wq, Wk, Wv, Wo);
    qkv_gemm<<<dim3(6, 384), 256, gemm_smem>>>();
    attn16<<<S_DIM * NH, 384, attn_smem>>>();
    out_gemm<<<dim3(2, 384), 256, gemm_smem>>>(out);
}